// round 7
// baseline (speedup 1.0000x reference)
#include <cuda_runtime.h>
#include <cuda_bf16.h>
#include <cstdint>

#define L2E   1.44269504088896340736f
#define C1    (0.125f * L2E)
#define NEGA  (-1e9f * L2E)

#define TOT_ROWS (8 * 2048)

// preprocessed split planes: [row][64] bf16 as uint4 chunks (8 per row, 128 B)
__device__ __align__(16) uint4 g_qhi[TOT_ROWS * 8];
__device__ __align__(16) uint4 g_qlo[TOT_ROWS * 8];
__device__ __align__(16) uint4 g_khi[TOT_ROWS * 8];
__device__ __align__(16) uint4 g_klo[TOT_ROWS * 8];
__device__ __align__(16) uint4 g_vhi[TOT_ROWS * 8];
__device__ __align__(16) uint4 g_vlo[TOT_ROWS * 8];

// smem: two K/V buffers; per buffer planes (row stride 144 B, 64 rows):
#define SKHI 0
#define SKLO 9216
#define SVHI 18432
#define SVLO 27648
#define BUF  36864
#define SMEM_TOTAL (2 * BUF)

__device__ __forceinline__ uint32_t smem_u32(const void* p) {
    uint32_t a;
    asm("{ .reg .u64 t; cvta.to.shared.u64 t, %1; cvt.u32.u64 %0, t; }" : "=r"(a) : "l"(p));
    return a;
}
__device__ __forceinline__ float ex2f(float x) {
    float r; asm("ex2.approx.ftz.f32 %0, %1;" : "=f"(r) : "f"(x)); return r;
}
__device__ __forceinline__ void split2(float a, float b, uint32_t& hi, uint32_t& lo) {
    __nv_bfloat162 h = __floats2bfloat162_rn(a, b);
    float ra = a - __bfloat162float(h.x);
    float rb = b - __bfloat162float(h.y);
    __nv_bfloat162 l = __floats2bfloat162_rn(ra, rb);
    hi = *reinterpret_cast<const uint32_t*>(&h);
    lo = *reinterpret_cast<const uint32_t*>(&l);
}
__device__ __forceinline__ void cpa16(uint32_t dst, const void* src) {
    asm volatile("cp.async.cg.shared.global [%0], [%1], 16;" :: "r"(dst), "l"(src) : "memory");
}
#define CPA_COMMIT() asm volatile("cp.async.commit_group;" ::: "memory")
#define CPA_WAIT0()  asm volatile("cp.async.wait_group 0;" ::: "memory")
#define CPA_WAIT1()  asm volatile("cp.async.wait_group 1;" ::: "memory")

#define LDSM_X4(r0, r1, r2, r3, addr) \
    asm volatile("ldmatrix.sync.aligned.m8n8.x4.shared.b16 {%0,%1,%2,%3}, [%4];" \
        : "=r"(r0), "=r"(r1), "=r"(r2), "=r"(r3) : "r"(addr))
#define LDSM_X4T(r0, r1, r2, r3, addr) \
    asm volatile("ldmatrix.sync.aligned.m8n8.x4.trans.shared.b16 {%0,%1,%2,%3}, [%4];" \
        : "=r"(r0), "=r"(r1), "=r"(r2), "=r"(r3) : "r"(addr))

__device__ __forceinline__ void mma16816(float* d, const uint32_t* a, uint32_t b0, uint32_t b1) {
    asm volatile("mma.sync.aligned.m16n8k16.row.col.f32.bf16.bf16.f32 "
        "{%0,%1,%2,%3}, {%4,%5,%6,%7}, {%8,%9}, {%0,%1,%2,%3};"
        : "+f"(d[0]), "+f"(d[1]), "+f"(d[2]), "+f"(d[3])
        : "r"(a[0]), "r"(a[1]), "r"(a[2]), "r"(a[3]), "r"(b0), "r"(b1));
}

// ============ preprocess: split Q*C1, K, V*mv into bf16 hi/lo planes ============
__global__ void __launch_bounds__(256)
prep_kernel(const float4* __restrict__ Q, const float4* __restrict__ K,
            const float4* __restrict__ V, const float* __restrict__ MV) {
    int i = blockIdx.x * 256 + threadIdx.x;   // 0 .. TOT_ROWS*8 - 1
    int row = i >> 3, c8 = i & 7;
    int fb = row * 16 + c8 * 2;

    float4 a, b;
    uint4 hi, lo;

    a = Q[fb]; b = Q[fb + 1];
    a.x *= C1; a.y *= C1; a.z *= C1; a.w *= C1;
    b.x *= C1; b.y *= C1; b.z *= C1; b.w *= C1;
    split2(a.x, a.y, hi.x, lo.x); split2(a.z, a.w, hi.y, lo.y);
    split2(b.x, b.y, hi.z, lo.z); split2(b.z, b.w, hi.w, lo.w);
    g_qhi[i] = hi; g_qlo[i] = lo;

    a = K[fb]; b = K[fb + 1];
    split2(a.x, a.y, hi.x, lo.x); split2(a.z, a.w, hi.y, lo.y);
    split2(b.x, b.y, hi.z, lo.z); split2(b.z, b.w, hi.w, lo.w);
    g_khi[i] = hi; g_klo[i] = lo;

    float mv = MV[row];
    a = V[fb]; b = V[fb + 1];
    a.x *= mv; a.y *= mv; a.z *= mv; a.w *= mv;
    b.x *= mv; b.y *= mv; b.z *= mv; b.w *= mv;
    split2(a.x, a.y, hi.x, lo.x); split2(a.z, a.w, hi.y, lo.y);
    split2(b.x, b.y, hi.z, lo.z); split2(b.z, b.w, hi.w, lo.w);
    g_vhi[i] = hi; g_vlo[i] = lo;
}

// ============ main attention kernel ============
// B=8, S=2048, D=64. grid=(16,8), 256 threads = 8 warps x 16 q-rows.
__global__ void __launch_bounds__(256, 1)
attn_mma_kernel(const float* __restrict__ MQ, const float* __restrict__ MK,
                float* __restrict__ out) {
    extern __shared__ __align__(16) unsigned char smem_raw[];
    __shared__ float mks[2][64];
    const uint32_t sb = smem_u32(smem_raw);

    const int tid  = threadIdx.x;
    const int w    = tid >> 5;
    const int lane = tid & 31;
    const int g    = lane >> 2;
    const int tq   = lane & 3;
    const int la_r = (lane & 7) + (lane & 8);           // A / V-trans row pattern
    const int la_c = (lane >> 4) << 3;
    const int lb_r = (lane & 7) + ((lane >> 4) << 3);   // K B row pattern
    const int lb_c = (lane & 8);

    const int b  = blockIdx.y;
    const int q0 = blockIdx.x * 128;
    const size_t base = (size_t)b * 2048;

    const int ld_row = tid >> 3;     // 0..31
    const int ld_col = tid & 7;      // 0..7

    // ---- stage split Q (128x64, hi+lo) via cp.async into buf0 region ----
    {
        const size_t qrb = (size_t)(base + q0) * 128;
        const char* qh = (const char*)g_qhi + qrb;
        const char* ql = (const char*)g_qlo + qrb;
#pragma unroll
        for (int t = 0; t < 4; t++) {
            int row = ld_row + 32 * t;
            cpa16(sb + row * 144 + ld_col * 16, qh + (size_t)row * 128 + ld_col * 16);
            cpa16(sb + 18432 + row * 144 + ld_col * 16, ql + (size_t)row * 128 + ld_col * 16);
        }
        CPA_COMMIT();
    }
    CPA_WAIT0();
    __syncthreads();

    // ---- persistent Q fragments (rows 16w..16w+15, 4 k-chunks, hi/lo) ----
    uint32_t qh[4][4], ql[4][4];
#pragma unroll
    for (int kc = 0; kc < 4; kc++) {
        uint32_t off = (uint32_t)((16 * w + la_r) * 144 + (kc * 16 + la_c) * 2);
        LDSM_X4(qh[kc][0], qh[kc][1], qh[kc][2], qh[kc][3], sb + off);
        LDSM_X4(ql[kc][0], ql[kc][1], ql[kc][2], ql[kc][3], sb + 18432 + off);
    }
    __syncthreads();   // Q reads done; buf0 reusable

    const float mqa = MQ[base + q0 + 16 * w + g];
    const float mqb = MQ[base + q0 + 16 * w + g + 8];
    const float bqa = -NEGA * mqa;
    const float bqb = -NEGA * mqb;

    float o[8][4];
#pragma unroll
    for (int n = 0; n < 8; n++)
#pragma unroll
        for (int c = 0; c < 4; c++) o[n][c] = 0.f;
    float lr0 = 0.f, lr1 = 0.f;

    // tile issue: 4 planes x 64 rows x 128 B, 8 chunks/thread
#define ISSUE_TILE(k0, bufb)                                                     \
    {                                                                            \
        const size_t rb = (size_t)(base + (k0)) * 128 +                          \
                          (size_t)ld_col * 16;                                   \
        const int r0 = ld_row, r1 = ld_row + 32;                                 \
        const uint32_t dc = (bufb) + ld_col * 16;                                \
        cpa16(dc + SKHI + r0 * 144, (const char*)g_khi + rb + (size_t)r0 * 128); \
        cpa16(dc + SKHI + r1 * 144, (const char*)g_khi + rb + (size_t)r1 * 128); \
        cpa16(dc + SKLO + r0 * 144, (const char*)g_klo + rb + (size_t)r0 * 128); \
        cpa16(dc + SKLO + r1 * 144, (const char*)g_klo + rb + (size_t)r1 * 128); \
        cpa16(dc + SVHI + r0 * 144, (const char*)g_vhi + rb + (size_t)r0 * 128); \
        cpa16(dc + SVHI + r1 * 144, (const char*)g_vhi + rb + (size_t)r1 * 128); \
        cpa16(dc + SVLO + r0 * 144, (const char*)g_vlo + rb + (size_t)r0 * 128); \
        cpa16(dc + SVLO + r1 * 144, (const char*)g_vlo + rb + (size_t)r1 * 128); \
        CPA_COMMIT();                                                            \
    }

    ISSUE_TILE(0, sb);
    ISSUE_TILE(64, sb + BUF);
    if (tid < 64) {
        mks[0][tid] = MK[base + tid];
        mks[1][tid] = MK[base + 64 + tid];
    }

    for (int kt = 0; kt < 32; kt++) {
        const uint32_t cur = sb + (uint32_t)(kt & 1) * BUF;
        const int mb = kt & 1;

        if (kt < 31) { CPA_WAIT1(); } else { CPA_WAIT0(); }
        __syncthreads();

        // ---- S = Q K^T (16 x 64 per warp), 3-split ----
        float s[8][4];
#pragma unroll
        for (int n = 0; n < 8; n++)
#pragma unroll
            for (int c = 0; c < 4; c++) s[n][c] = 0.f;

#pragma unroll
        for (int kc = 0; kc < 4; kc++) {
#pragma unroll
            for (int np = 0; np < 4; np++) {
                uint32_t off = (uint32_t)((np * 16 + lb_r) * 144 + (kc * 16 + lb_c) * 2);
                uint32_t bh0, bh1, bh2, bh3, bl0, bl1, bl2, bl3;
                LDSM_X4(bh0, bh1, bh2, bh3, cur + SKHI + off);
                LDSM_X4(bl0, bl1, bl2, bl3, cur + SKLO + off);
                mma16816(s[2 * np],     qh[kc], bh0, bh1);
                mma16816(s[2 * np],     ql[kc], bh0, bh1);
                mma16816(s[2 * np],     qh[kc], bl0, bl1);
                mma16816(s[2 * np + 1], qh[kc], bh2, bh3);
                mma16816(s[2 * np + 1], ql[kc], bh2, bh3);
                mma16816(s[2 * np + 1], qh[kc], bl2, bl3);
            }
        }

        // ---- softmax (C1 pre-folded into Q; exact mask term) -> P fragments ----
        uint32_t ph[4][4], pl[4][4];
#pragma unroll
        for (int n = 0; n < 8; n++) {
            int col0 = 8 * n + 2 * tq;
            float mk0 = mks[mb][col0], mk1 = mks[mb][col0 + 1];
            float t00 = fmaf(bqa, mk0, NEGA);
            float t01 = fmaf(bqa, mk1, NEGA);
            float t10 = fmaf(bqb, mk0, NEGA);
            float t11 = fmaf(bqb, mk1, NEGA);
            float p0 = ex2f(s[n][0] + t00);
            float p1 = ex2f(s[n][1] + t01);
            float p2 = ex2f(s[n][2] + t10);
            float p3 = ex2f(s[n][3] + t11);
            lr0 += p0 + p1;
            lr1 += p2 + p3;
            split2(p0, p1, ph[n >> 1][(n & 1) * 2],     pl[n >> 1][(n & 1) * 2]);
            split2(p2, p3, ph[n >> 1][(n & 1) * 2 + 1], pl[n >> 1][(n & 1) * 2 + 1]);
        }

        // ---- O += P V (V via ldmatrix.trans), 3-split ----
#pragma unroll
        for (int kc = 0; kc < 4; kc++) {
#pragma unroll
            for (int dp = 0; dp < 4; dp++) {
                uint32_t off = (uint32_t)((kc * 16 + la_r) * 144 + (dp * 16 + la_c) * 2);
                uint32_t bh0, bh1, bh2, bh3, bl0, bl1, bl2, bl3;
                LDSM_X4T(bh0, bh1, bh2, bh3, cur + SVHI + off);
                LDSM_X4T(bl0, bl1, bl2, bl3, cur + SVLO + off);
                mma16816(o[2 * dp],     ph[kc], bh0, bh1);
                mma16816(o[2 * dp],     pl[kc], bh0, bh1);
                mma16816(o[2 * dp],     ph[kc], bl0, bl1);
                mma16816(o[2 * dp + 1], ph[kc], bh2, bh3);
                mma16816(o[2 * dp + 1], pl[kc], bh2, bh3);
                mma16816(o[2 * dp + 1], ph[kc], bl2, bl3);
            }
        }

        __syncthreads();   // all reads of cur done before refill
        if (kt < 30) {
            ISSUE_TILE((kt + 2) * 64, cur);
            if (tid < 64) mks[mb][tid] = MK[base + (kt + 2) * 64 + tid];
        }
    }

    // ---- epilogue: reduce row sums across the 4 lanes sharing a row ----
    lr0 += __shfl_xor_sync(0xffffffffu, lr0, 1);
    lr0 += __shfl_xor_sync(0xffffffffu, lr0, 2);
    lr1 += __shfl_xor_sync(0xffffffffu, lr1, 1);
    lr1 += __shfl_xor_sync(0xffffffffu, lr1, 2);
    const float inv0 = 1.0f / lr0;
    const float inv1 = 1.0f / lr1;

    const size_t row0 = base + q0 + 16 * w + g;
    const size_t row1 = row0 + 8;
#pragma unroll
    for (int n = 0; n < 8; n++) {
        float2 v0 = make_float2(o[n][0] * inv0, o[n][1] * inv0);
        float2 v1 = make_float2(o[n][2] * inv1, o[n][3] * inv1);
        *reinterpret_cast<float2*>(out + row0 * 64 + 8 * n + 2 * tq) = v0;
        *reinterpret_cast<float2*>(out + row1 * 64 + 8 * n + 2 * tq) = v1;
    }
}

extern "C" void kernel_launch(void* const* d_in, const int* in_sizes, int n_in,
                              void* d_out, int out_size) {
    const float* Q  = (const float*)d_in[0];
    const float* K  = (const float*)d_in[1];
    const float* V  = (const float*)d_in[2];
    const float* MQ = (const float*)d_in[3];
    const float* MK = (const float*)d_in[4];
    const float* MV = (const float*)d_in[5];
    float* out = (float*)d_out;

    prep_kernel<<<TOT_ROWS * 8 / 256, 256>>>(
        (const float4*)Q, (const float4*)K, (const float4*)V, MV);

    cudaFuncSetAttribute(attn_mma_kernel, cudaFuncAttributeMaxDynamicSharedMemorySize, SMEM_TOTAL);
    dim3 grid(16, 8);
    attn_mma_kernel<<<grid, 256, SMEM_TOTAL>>>(MQ, MK, out);
}

// round 8
// speedup vs baseline: 1.2210x; 1.2210x over previous
#include <cuda_runtime.h>
#include <cuda_bf16.h>
#include <cstdint>

#define L2E   1.44269504088896340736f
#define C1    (0.125f * L2E)
#define NEGA  (-1e9f * L2E)

// smem byte offsets (union: Q staging overlays K/V tile buffers)
#define SQHI 0
#define SQLO 18432
#define SKHI 0
#define SKLO 9216
#define SVHI 18432
#define SVLO 27648
// bf16 row stride = 72 elems (144 B): ldmatrix 8-row bursts hit distinct banks

__device__ __forceinline__ uint32_t smem_u32(const void* p) {
    uint32_t a;
    asm("{ .reg .u64 t; cvta.to.shared.u64 t, %1; cvt.u32.u64 %0, t; }" : "=r"(a) : "l"(p));
    return a;
}
__device__ __forceinline__ float ex2f(float x) {
    float r; asm("ex2.approx.ftz.f32 %0, %1;" : "=f"(r) : "f"(x)); return r;
}
__device__ __forceinline__ void sts64(uint32_t a, uint32_t x, uint32_t y) {
    asm volatile("st.shared.v2.b32 [%0], {%1,%2};" :: "r"(a), "r"(x), "r"(y) : "memory");
}
// split two f32 -> bf16x2 hi word + bf16x2 lo word (elem0 in low half)
__device__ __forceinline__ void split2(float a, float b, uint32_t& hi, uint32_t& lo) {
    __nv_bfloat162 h = __floats2bfloat162_rn(a, b);
    float ra = a - __bfloat162float(h.x);
    float rb = b - __bfloat162float(h.y);
    __nv_bfloat162 l = __floats2bfloat162_rn(ra, rb);
    hi = *reinterpret_cast<const uint32_t*>(&h);
    lo = *reinterpret_cast<const uint32_t*>(&l);
}

#define LDSM_X4(r0, r1, r2, r3, addr) \
    asm volatile("ldmatrix.sync.aligned.m8n8.x4.shared.b16 {%0,%1,%2,%3}, [%4];" \
        : "=r"(r0), "=r"(r1), "=r"(r2), "=r"(r3) : "r"(addr))
#define LDSM_X4T(r0, r1, r2, r3, addr) \
    asm volatile("ldmatrix.sync.aligned.m8n8.x4.trans.shared.b16 {%0,%1,%2,%3}, [%4];" \
        : "=r"(r0), "=r"(r1), "=r"(r2), "=r"(r3) : "r"(addr))

__device__ __forceinline__ void mma16816(float* d, const uint32_t* a, uint32_t b0, uint32_t b1) {
    asm volatile("mma.sync.aligned.m16n8k16.row.col.f32.bf16.bf16.f32 "
        "{%0,%1,%2,%3}, {%4,%5,%6,%7}, {%8,%9}, {%0,%1,%2,%3};"
        : "+f"(d[0]), "+f"(d[1]), "+f"(d[2]), "+f"(d[3])
        : "r"(a[0]), "r"(a[1]), "r"(a[2]), "r"(a[3]), "r"(b0), "r"(b1));
}

// B=8, S=2048, D=64. grid=(16,8), 256 threads = 8 warps x 16 q-rows.
__global__ void __launch_bounds__(256, 1)
attn_mma_kernel(const float* __restrict__ Q, const float* __restrict__ K,
                const float* __restrict__ V, const float* __restrict__ MQ,
                const float* __restrict__ MK, const float* __restrict__ MV,
                float* __restrict__ out) {
    __shared__ __align__(16) unsigned char smbuf[36864];
    __shared__ float mks[64];
    const uint32_t sb = smem_u32(smbuf);

    const int tid  = threadIdx.x;
    const int w    = tid >> 5;
    const int lane = tid & 31;
    const int g    = lane >> 2;       // row-in-8 group
    const int tq   = lane & 3;        // col-pair index
    // ldmatrix per-lane offsets
    const int la_r  = (lane & 7) + (lane & 8);   // A/V pattern row
    const int la_c  = (lane >> 4) << 3;          // A/V pattern col +8
    const int lb_r  = (lane & 7) + ((lane >> 4) << 3);  // K B pattern row
    const int lb_c  = (lane & 8);                       // K B pattern col +8

    const int b  = blockIdx.y;
    const int q0 = blockIdx.x * 128;
    const size_t base = (size_t)b * 2048;

    const float4* Q4 = reinterpret_cast<const float4*>(Q);
    const float4* K4 = reinterpret_cast<const float4*>(K);
    const float4* V4 = reinterpret_cast<const float4*>(V);

    // ---- stage Q (128x64) split into smem ----
#pragma unroll
    for (int t = 0; t < 8; t++) {
        int idx = tid + 256 * t;
        int r = idx >> 4, c4 = idx & 15;
        float4 q = Q4[(base + q0 + r) * 16 + c4];
        uint32_t h0, l0, h1, l1;
        split2(q.x, q.y, h0, l0);
        split2(q.z, q.w, h1, l1);
        uint32_t off = (uint32_t)(r * 144 + c4 * 8);
        sts64(sb + SQHI + off, h0, h1);
        sts64(sb + SQLO + off, l0, l1);
    }
    __syncthreads();

    // ---- load persistent Q fragments (rows 16w..16w+15, 4 k-chunks, hi/lo) ----
    uint32_t qh[4][4], ql[4][4];
#pragma unroll
    for (int kc = 0; kc < 4; kc++) {
        uint32_t off = (uint32_t)((16 * w + la_r) * 144 + (kc * 16 + la_c) * 2);
        LDSM_X4(qh[kc][0], qh[kc][1], qh[kc][2], qh[kc][3], sb + SQHI + off);
        LDSM_X4(ql[kc][0], ql[kc][1], ql[kc][2], ql[kc][3], sb + SQLO + off);
    }

    const float mqa = MQ[base + q0 + 16 * w + g];
    const float mqb = MQ[base + q0 + 16 * w + g + 8];
    const float bqa = -NEGA * mqa;
    const float bqb = -NEGA * mqb;

    float o[8][4];
#pragma unroll
    for (int n = 0; n < 8; n++)
#pragma unroll
        for (int c = 0; c < 4; c++) o[n][c] = 0.f;
    float lr0 = 0.f, lr1 = 0.f;

    // ---- prefetch tile 0 ----
    float4 kreg[4], vreg[4];
    float  mvr[4], mk_in;
#pragma unroll
    for (int t = 0; t < 4; t++) {
        int idx = tid + 256 * t;
        int r = idx >> 4, c4 = idx & 15;
        kreg[t] = K4[(base + r) * 16 + c4];
        vreg[t] = V4[(base + r) * 16 + c4];
        mvr[t]  = MV[base + r];
    }
    mk_in = (tid < 64) ? MK[base + tid] : 0.f;

    for (int kt = 0; kt < 32; kt++) {
        __syncthreads();   // prior tile's smem reads (or Q ldsm) complete

        // ---- store K/V split tiles ----
#pragma unroll
        for (int t = 0; t < 4; t++) {
            int idx = tid + 256 * t;
            int r = idx >> 4, c4 = idx & 15;
            uint32_t off = (uint32_t)(r * 144 + c4 * 8);
            uint32_t h0, l0, h1, l1;
            split2(kreg[t].x, kreg[t].y, h0, l0);
            split2(kreg[t].z, kreg[t].w, h1, l1);
            sts64(sb + SKHI + off, h0, h1);
            sts64(sb + SKLO + off, l0, l1);
            float m = mvr[t];
            split2(vreg[t].x * m, vreg[t].y * m, h0, l0);
            split2(vreg[t].z * m, vreg[t].w * m, h1, l1);
            sts64(sb + SVHI + off, h0, h1);
            sts64(sb + SVLO + off, l0, l1);
        }
        if (tid < 64) mks[tid] = mk_in;
        __syncthreads();

        // ---- S = Q K^T (16 x 64 per warp), 3-split, ILP-ordered ----
        float s[8][4];
#pragma unroll
        for (int n = 0; n < 8; n++)
#pragma unroll
            for (int c = 0; c < 4; c++) s[n][c] = 0.f;

#pragma unroll
        for (int kc = 0; kc < 4; kc++) {
            uint32_t bh[4][4], bl[4][4];
#pragma unroll
            for (int np = 0; np < 4; np++) {
                uint32_t off = (uint32_t)((np * 16 + lb_r) * 144 + (kc * 16 + lb_c) * 2);
                LDSM_X4(bh[np][0], bh[np][1], bh[np][2], bh[np][3], sb + SKHI + off);
                LDSM_X4(bl[np][0], bl[np][1], bl[np][2], bl[np][3], sb + SKLO + off);
            }
            // term-major, np-inner: accumulator reuse distance = 8 MMAs
#pragma unroll
            for (int np = 0; np < 4; np++) {
                mma16816(s[2 * np],     qh[kc], bh[np][0], bh[np][1]);
                mma16816(s[2 * np + 1], qh[kc], bh[np][2], bh[np][3]);
            }
#pragma unroll
            for (int np = 0; np < 4; np++) {
                mma16816(s[2 * np],     ql[kc], bh[np][0], bh[np][1]);
                mma16816(s[2 * np + 1], ql[kc], bh[np][2], bh[np][3]);
            }
#pragma unroll
            for (int np = 0; np < 4; np++) {
                mma16816(s[2 * np],     qh[kc], bl[np][0], bl[np][1]);
                mma16816(s[2 * np + 1], qh[kc], bl[np][2], bl[np][3]);
            }
        }

        // ---- softmax (no max-sub; exact mask term) + P fragments ----
        uint32_t ph[4][4], pl[4][4];
#pragma unroll
        for (int n = 0; n < 8; n++) {
            int col0 = 8 * n + 2 * tq;
            float mk0 = mks[col0], mk1 = mks[col0 + 1];
            float t00 = fmaf(bqa, mk0, NEGA);
            float t01 = fmaf(bqa, mk1, NEGA);
            float t10 = fmaf(bqb, mk0, NEGA);
            float t11 = fmaf(bqb, mk1, NEGA);
            float p0 = ex2f(fmaf(s[n][0], C1, t00));
            float p1 = ex2f(fmaf(s[n][1], C1, t01));
            float p2 = ex2f(fmaf(s[n][2], C1, t10));
            float p3 = ex2f(fmaf(s[n][3], C1, t11));
            lr0 += p0 + p1;
            lr1 += p2 + p3;
            split2(p0, p1, ph[n >> 1][(n & 1) * 2],     pl[n >> 1][(n & 1) * 2]);
            split2(p2, p3, ph[n >> 1][(n & 1) * 2 + 1], pl[n >> 1][(n & 1) * 2 + 1]);
        }

        // ---- prefetch next tile (overlaps PV mma) ----
        if (kt < 31) {
            const int k0n = (kt + 1) * 64;
#pragma unroll
            for (int t = 0; t < 4; t++) {
                int idx = tid + 256 * t;
                int r = idx >> 4, c4 = idx & 15;
                kreg[t] = K4[(base + k0n + r) * 16 + c4];
                vreg[t] = V4[(base + k0n + r) * 16 + c4];
                mvr[t]  = MV[base + k0n + r];
            }
            mk_in = (tid < 64) ? MK[base + k0n + tid] : 0.f;
        }

        // ---- O += P V (V via ldmatrix.trans), 3-split, ILP-ordered ----
#pragma unroll
        for (int kc = 0; kc < 4; kc++) {
            uint32_t vh[4][4], vl[4][4];
#pragma unroll
            for (int dp = 0; dp < 4; dp++) {
                uint32_t off = (uint32_t)((kc * 16 + la_r) * 144 + (dp * 16 + la_c) * 2);
                LDSM_X4T(vh[dp][0], vh[dp][1], vh[dp][2], vh[dp][3], sb + SVHI + off);
                LDSM_X4T(vl[dp][0], vl[dp][1], vl[dp][2], vl[dp][3], sb + SVLO + off);
            }
#pragma unroll
            for (int dp = 0; dp < 4; dp++) {
                mma16816(o[2 * dp],     ph[kc], vh[dp][0], vh[dp][1]);
                mma16816(o[2 * dp + 1], ph[kc], vh[dp][2], vh[dp][3]);
            }
#pragma unroll
            for (int dp = 0; dp < 4; dp++) {
                mma16816(o[2 * dp],     pl[kc], vh[dp][0], vh[dp][1]);
                mma16816(o[2 * dp + 1], pl[kc], vh[dp][2], vh[dp][3]);
            }
#pragma unroll
            for (int dp = 0; dp < 4; dp++) {
                mma16816(o[2 * dp],     ph[kc], vl[dp][0], vl[dp][1]);
                mma16816(o[2 * dp + 1], ph[kc], vl[dp][2], vl[dp][3]);
            }
        }
    }

    // ---- epilogue: reduce row sums across the 4 lanes sharing a row ----
    lr0 += __shfl_xor_sync(0xffffffffu, lr0, 1);
    lr0 += __shfl_xor_sync(0xffffffffu, lr0, 2);
    lr1 += __shfl_xor_sync(0xffffffffu, lr1, 1);
    lr1 += __shfl_xor_sync(0xffffffffu, lr1, 2);
    const float inv0 = 1.0f / lr0;
    const float inv1 = 1.0f / lr1;

    const size_t row0 = base + q0 + 16 * w + g;
    const size_t row1 = row0 + 8;
#pragma unroll
    for (int n = 0; n < 8; n++) {
        float2 v0 = make_float2(o[n][0] * inv0, o[n][1] * inv0);
        float2 v1 = make_float2(o[n][2] * inv1, o[n][3] * inv1);
        *reinterpret_cast<float2*>(out + row0 * 64 + 8 * n + 2 * tq) = v0;
        *reinterpret_cast<float2*>(out + row1 * 64 + 8 * n + 2 * tq) = v1;
    }
}

extern "C" void kernel_launch(void* const* d_in, const int* in_sizes, int n_in,
                              void* d_out, int out_size) {
    const float* Q  = (const float*)d_in[0];
    const float* K  = (const float*)d_in[1];
    const float* V  = (const float*)d_in[2];
    const float* MQ = (const float*)d_in[3];
    const float* MK = (const float*)d_in[4];
    const float* MV = (const float*)d_in[5];
    float* out = (float*)d_out;

    dim3 grid(16, 8);
    attn_mma_kernel<<<grid, 256>>>(Q, K, V, MQ, MK, MV, out);
}

// round 9
// speedup vs baseline: 1.2215x; 1.0004x over previous
#include <cuda_runtime.h>
#include <cuda_bf16.h>
#include <cstdint>

#define L2E   1.44269504088896340736f
#define C1    (0.125f * L2E)
#define NEGA  (-1e9f * L2E)

// smem byte offsets (union: Q staging overlays K/V tile buffers)
#define SQHI 0
#define SQLO 18432
#define SKHI 0
#define SKLO 9216
#define SVHI 18432
#define SVLO 27648
// bf16 row stride = 72 elems (144 B): ldmatrix 8-row bursts hit distinct banks

__device__ __forceinline__ uint32_t smem_u32(const void* p) {
    uint32_t a;
    asm("{ .reg .u64 t; cvta.to.shared.u64 t, %1; cvt.u32.u64 %0, t; }" : "=r"(a) : "l"(p));
    return a;
}
__device__ __forceinline__ float ex2f(float x) {
    float r; asm("ex2.approx.ftz.f32 %0, %1;" : "=f"(r) : "f"(x)); return r;
}
__device__ __forceinline__ void sts64(uint32_t a, uint32_t x, uint32_t y) {
    asm volatile("st.shared.v2.b32 [%0], {%1,%2};" :: "r"(a), "r"(x), "r"(y) : "memory");
}
// split two f32 -> bf16x2 hi word + bf16x2 lo word (elem0 in low half)
__device__ __forceinline__ void split2(float a, float b, uint32_t& hi, uint32_t& lo) {
    __nv_bfloat162 h = __floats2bfloat162_rn(a, b);
    float ra = a - __bfloat162float(h.x);
    float rb = b - __bfloat162float(h.y);
    __nv_bfloat162 l = __floats2bfloat162_rn(ra, rb);
    hi = *reinterpret_cast<const uint32_t*>(&h);
    lo = *reinterpret_cast<const uint32_t*>(&l);
}

#define LDSM_X4(r0, r1, r2, r3, addr) \
    asm volatile("ldmatrix.sync.aligned.m8n8.x4.shared.b16 {%0,%1,%2,%3}, [%4];" \
        : "=r"(r0), "=r"(r1), "=r"(r2), "=r"(r3) : "r"(addr))
#define LDSM_X4T(r0, r1, r2, r3, addr) \
    asm volatile("ldmatrix.sync.aligned.m8n8.x4.trans.shared.b16 {%0,%1,%2,%3}, [%4];" \
        : "=r"(r0), "=r"(r1), "=r"(r2), "=r"(r3) : "r"(addr))

__device__ __forceinline__ void mma16816(float* d, const uint32_t* a, uint32_t b0, uint32_t b1) {
    asm volatile("mma.sync.aligned.m16n8k16.row.col.f32.bf16.bf16.f32 "
        "{%0,%1,%2,%3}, {%4,%5,%6,%7}, {%8,%9}, {%0,%1,%2,%3};"
        : "+f"(d[0]), "+f"(d[1]), "+f"(d[2]), "+f"(d[3])
        : "r"(a[0]), "r"(a[1]), "r"(a[2]), "r"(a[3]), "r"(b0), "r"(b1));
}

// B=8, S=2048, D=64. grid=(16,8), 256 threads = 8 warps x 16 q-rows.
__global__ void __launch_bounds__(256, 1)
attn_mma_kernel(const float* __restrict__ Q, const float* __restrict__ K,
                const float* __restrict__ V, const float* __restrict__ MQ,
                const float* __restrict__ MK, const float* __restrict__ MV,
                float* __restrict__ out) {
    __shared__ __align__(16) unsigned char smbuf[36864];
    __shared__ float mks[64];
    const uint32_t sb = smem_u32(smbuf);

    const int tid  = threadIdx.x;
    const int w    = tid >> 5;
    const int lane = tid & 31;
    const int g    = lane >> 2;       // row-in-8 group
    const int tq   = lane & 3;        // col-pair index
    // ldmatrix per-lane offsets
    const int la_r  = (lane & 7) + (lane & 8);   // A/V pattern row
    const int la_c  = (lane >> 4) << 3;          // A/V pattern col +8
    const int lb_r  = (lane & 7) + ((lane >> 4) << 3);  // K B pattern row
    const int lb_c  = (lane & 8);                       // K B pattern col +8

    const int b  = blockIdx.y;
    const int q0 = blockIdx.x * 128;
    const size_t base = (size_t)b * 2048;

    const float4* Q4 = reinterpret_cast<const float4*>(Q);
    const float4* K4 = reinterpret_cast<const float4*>(K);
    const float4* V4 = reinterpret_cast<const float4*>(V);

    // ---- stage Q (128x64) split into smem ----
#pragma unroll
    for (int t = 0; t < 8; t++) {
        int idx = tid + 256 * t;
        int r = idx >> 4, c4 = idx & 15;
        float4 q = Q4[(base + q0 + r) * 16 + c4];
        uint32_t h0, l0, h1, l1;
        split2(q.x, q.y, h0, l0);
        split2(q.z, q.w, h1, l1);
        uint32_t off = (uint32_t)(r * 144 + c4 * 8);
        sts64(sb + SQHI + off, h0, h1);
        sts64(sb + SQLO + off, l0, l1);
    }
    __syncthreads();

    // ---- load persistent Q fragments (rows 16w..16w+15, 4 k-chunks, hi/lo) ----
    uint32_t qh[4][4], ql[4][4];
#pragma unroll
    for (int kc = 0; kc < 4; kc++) {
        uint32_t off = (uint32_t)((16 * w + la_r) * 144 + (kc * 16 + la_c) * 2);
        LDSM_X4(qh[kc][0], qh[kc][1], qh[kc][2], qh[kc][3], sb + SQHI + off);
        LDSM_X4(ql[kc][0], ql[kc][1], ql[kc][2], ql[kc][3], sb + SQLO + off);
    }

    const float mqa = MQ[base + q0 + 16 * w + g];
    const float mqb = MQ[base + q0 + 16 * w + g + 8];
    const float bqa = -NEGA * mqa;
    const float bqb = -NEGA * mqb;

    float o[8][4];
#pragma unroll
    for (int n = 0; n < 8; n++)
#pragma unroll
        for (int c = 0; c < 4; c++) o[n][c] = 0.f;
    float lr0 = 0.f, lr1 = 0.f;

    // ---- prefetch tile 0 ----
    float4 kreg[4], vreg[4];
    float  mvr[4], mk_in;
#pragma unroll
    for (int t = 0; t < 4; t++) {
        int idx = tid + 256 * t;
        int r = idx >> 4, c4 = idx & 15;
        kreg[t] = K4[(base + r) * 16 + c4];
        vreg[t] = V4[(base + r) * 16 + c4];
        mvr[t]  = MV[base + r];
    }
    mk_in = (tid < 64) ? MK[base + tid] : 0.f;

    for (int kt = 0; kt < 32; kt++) {
        __syncthreads();   // prior tile's smem reads (or Q ldsm) complete

        // ---- store K/V split tiles ----
#pragma unroll
        for (int t = 0; t < 4; t++) {
            int idx = tid + 256 * t;
            int r = idx >> 4, c4 = idx & 15;
            uint32_t off = (uint32_t)(r * 144 + c4 * 8);
            uint32_t h0, l0, h1, l1;
            split2(kreg[t].x, kreg[t].y, h0, l0);
            split2(kreg[t].z, kreg[t].w, h1, l1);
            sts64(sb + SKHI + off, h0, h1);
            sts64(sb + SKLO + off, l0, l1);
            float m = mvr[t];
            split2(vreg[t].x * m, vreg[t].y * m, h0, l0);
            split2(vreg[t].z * m, vreg[t].w * m, h1, l1);
            sts64(sb + SVHI + off, h0, h1);
            sts64(sb + SVLO + off, l0, l1);
        }
        if (tid < 64) mks[tid] = mk_in;
        __syncthreads();

        // ---- S = Q K^T (16 x 64 per warp), 3-split ----
        float s[8][4];
#pragma unroll
        for (int n = 0; n < 8; n++)
#pragma unroll
            for (int c = 0; c < 4; c++) s[n][c] = 0.f;

#pragma unroll
        for (int kc = 0; kc < 4; kc++) {
#pragma unroll
            for (int np = 0; np < 4; np++) {
                uint32_t off = (uint32_t)((np * 16 + lb_r) * 144 + (kc * 16 + lb_c) * 2);
                uint32_t bh0, bh1, bh2, bh3, bl0, bl1, bl2, bl3;
                LDSM_X4(bh0, bh1, bh2, bh3, sb + SKHI + off);
                LDSM_X4(bl0, bl1, bl2, bl3, sb + SKLO + off);
                mma16816(s[2 * np],     qh[kc], bh0, bh1);
                mma16816(s[2 * np],     ql[kc], bh0, bh1);
                mma16816(s[2 * np],     qh[kc], bl0, bl1);
                mma16816(s[2 * np + 1], qh[kc], bh2, bh3);
                mma16816(s[2 * np + 1], ql[kc], bh2, bh3);
                mma16816(s[2 * np + 1], qh[kc], bl2, bl3);
            }
        }

        // ---- prefetch next tile (latency covered by softmax+PV below) ----
        if (kt < 31) {
            const int k0n = (kt + 1) * 64;
#pragma unroll
            for (int t = 0; t < 4; t++) {
                int idx = tid + 256 * t;
                int r = idx >> 4, c4 = idx & 15;
                kreg[t] = K4[(base + k0n + r) * 16 + c4];
                vreg[t] = V4[(base + k0n + r) * 16 + c4];
                mvr[t]  = MV[base + k0n + r];
            }
            mk_in = (tid < 64) ? MK[base + k0n + tid] : 0.f;
        }

        // ---- FUSED softmax + PV: per kc, exp 2 n-chunks then MMA that kc ----
        // interleaves MUFU/FMA work with TENSOR work inside each warp's stream
#pragma unroll
        for (int kc = 0; kc < 4; kc++) {
            uint32_t phv[4], plv[4];
#pragma unroll
            for (int h = 0; h < 2; h++) {
                const int n = 2 * kc + h;
                int col0 = 8 * n + 2 * tq;
                float mk0 = mks[col0], mk1 = mks[col0 + 1];
                float t00 = fmaf(bqa, mk0, NEGA);
                float t01 = fmaf(bqa, mk1, NEGA);
                float t10 = fmaf(bqb, mk0, NEGA);
                float t11 = fmaf(bqb, mk1, NEGA);
                float p0 = ex2f(fmaf(s[n][0], C1, t00));
                float p1 = ex2f(fmaf(s[n][1], C1, t01));
                float p2 = ex2f(fmaf(s[n][2], C1, t10));
                float p3 = ex2f(fmaf(s[n][3], C1, t11));
                lr0 += p0 + p1;
                lr1 += p2 + p3;
                split2(p0, p1, phv[h * 2],     plv[h * 2]);
                split2(p2, p3, phv[h * 2 + 1], plv[h * 2 + 1]);
            }
            // PV chunk kc: O += P[:,16kc:16kc+16] @ V[16kc:16kc+16,:]
#pragma unroll
            for (int dp = 0; dp < 4; dp++) {
                uint32_t off = (uint32_t)((kc * 16 + la_r) * 144 + (dp * 16 + la_c) * 2);
                uint32_t vh0, vh1, vh2, vh3, vl0, vl1, vl2, vl3;
                LDSM_X4T(vh0, vh1, vh2, vh3, sb + SVHI + off);
                LDSM_X4T(vl0, vl1, vl2, vl3, sb + SVLO + off);
                mma16816(o[2 * dp],     phv, vh0, vh1);
                mma16816(o[2 * dp],     plv, vh0, vh1);
                mma16816(o[2 * dp],     phv, vl0, vl1);
                mma16816(o[2 * dp + 1], phv, vh2, vh3);
                mma16816(o[2 * dp + 1], plv, vh2, vh3);
                mma16816(o[2 * dp + 1], phv, vl2, vl3);
            }
        }
    }

    // ---- epilogue: reduce row sums across the 4 lanes sharing a row ----
    lr0 += __shfl_xor_sync(0xffffffffu, lr0, 1);
    lr0 += __shfl_xor_sync(0xffffffffu, lr0, 2);
    lr1 += __shfl_xor_sync(0xffffffffu, lr1, 1);
    lr1 += __shfl_xor_sync(0xffffffffu, lr1, 2);
    const float inv0 = 1.0f / lr0;
    const float inv1 = 1.0f / lr1;

    const size_t row0 = base + q0 + 16 * w + g;
    const size_t row1 = row0 + 8;
#pragma unroll
    for (int n = 0; n < 8; n++) {
        float2 v0 = make_float2(o[n][0] * inv0, o[n][1] * inv0);
        float2 v1 = make_float2(o[n][2] * inv1, o[n][3] * inv1);
        *reinterpret_cast<float2*>(out + row0 * 64 + 8 * n + 2 * tq) = v0;
        *reinterpret_cast<float2*>(out + row1 * 64 + 8 * n + 2 * tq) = v1;
    }
}

extern "C" void kernel_launch(void* const* d_in, const int* in_sizes, int n_in,
                              void* d_out, int out_size) {
    const float* Q  = (const float*)d_in[0];
    const float* K  = (const float*)d_in[1];
    const float* V  = (const float*)d_in[2];
    const float* MQ = (const float*)d_in[3];
    const float* MK = (const float*)d_in[4];
    const float* MV = (const float*)d_in[5];
    float* out = (float*)d_out;

    dim3 grid(16, 8);
    attn_mma_kernel<<<grid, 256>>>(Q, K, V, MQ, MK, MV, out);
}